// round 5
// baseline (speedup 1.0000x reference)
#include <cuda_runtime.h>
#include <stdint.h>
#include <math.h>

typedef unsigned long long ull;

#define TSZ   524288u
#define TMASK 524287u
#define PI2   2654435761u
#define PI3   805459861u

// shared-memory float offsets (all weight-row starts 16B-aligned)
#define OW1 0       // [32,64]
#define OB1 2048    // [64]
#define OW2 2112    // [64,16]
#define OB2 3136    // [16]
#define OW3 3152    // [43,64]
#define OB3 5904    // [64]
#define OW4 5968    // [64,64]
#define OB4 10064   // [64]
#define OW5T 10128  // [3,64] transposed
#define OB5 10320   // [3] (+1 pad)
#define SW_TOTAL 10324

__device__ __forceinline__ void fma2(ull &c, ull a, ull b) {
    asm("fma.rn.f32x2 %0, %1, %2, %0;" : "+l"(c) : "l"(a), "l"(b));
}
__device__ __forceinline__ ull bcast2(float a) {
    ull r; asm("mov.b64 %0, {%1, %1};" : "=l"(r) : "f"(a), "f"(a)); return r;
}

union F2 { float2 f; ull u; };

__global__ __launch_bounds__(128, 3) void ngp_kernel(
    const float* __restrict__ x, const float* __restrict__ dirs,
    const float* __restrict__ tables,
    const float* __restrict__ w1, const float* __restrict__ b1,
    const float* __restrict__ w2, const float* __restrict__ b2,
    const float* __restrict__ w3, const float* __restrict__ b3,
    const float* __restrict__ w4, const float* __restrict__ b4,
    const float* __restrict__ w5, const float* __restrict__ b5,
    float* __restrict__ out, int n)
{
    __shared__ __align__(16) float sw[SW_TOTAL];
    const int tid = threadIdx.x;

    // cooperative weight staging (coalesced; sources L2-resident)
    for (int t = tid; t < 2048; t += 128) sw[OW1 + t] = w1[t];
    for (int t = tid; t < 64;   t += 128) sw[OB1 + t] = b1[t];
    for (int t = tid; t < 1024; t += 128) sw[OW2 + t] = w2[t];
    for (int t = tid; t < 16;   t += 128) sw[OB2 + t] = b2[t];
    for (int t = tid; t < 2752; t += 128) sw[OW3 + t] = w3[t];
    for (int t = tid; t < 64;   t += 128) sw[OB3 + t] = b3[t];
    for (int t = tid; t < 4096; t += 128) sw[OW4 + t] = w4[t];
    for (int t = tid; t < 64;   t += 128) sw[OB4 + t] = b4[t];
    for (int t = tid; t < 192;  t += 128) sw[OW5T + (t % 3) * 64 + (t / 3)] = w5[t];  // transpose
    if (tid < 3) sw[OB5 + tid] = b5[tid];
    __syncthreads();

    // two points per thread: A = first half of the block's 256, B = second half
    const int giA = blockIdx.x * 256 + tid;
    const int giB = giA + 128;
    const bool vA = (giA < n);
    const bool vB = (giB < n);
    const int  lA = vA ? giA : 0;
    const int  lB = vB ? giB : 0;

    // ---- positions, AABB masks, normalization ----
    const float INV3 = (1.0f / 3.0f);
    float pax = x[lA * 3 + 0] * INV3, pay = x[lA * 3 + 1] * INV3, paz = x[lA * 3 + 2] * INV3;
    float pbx = x[lB * 3 + 0] * INV3, pby = x[lB * 3 + 1] * INV3, pbz = x[lB * 3 + 2] * INV3;
    bool inA = (fabsf(pax) < 0.5f) && (fabsf(pay) < 0.5f) && (fabsf(paz) < 0.5f);
    bool inB = (fabsf(pbx) < 0.5f) && (fabsf(pby) < 0.5f) && (fabsf(pbz) < 0.5f);
    const float HI = 1.0f - 1e-7f;
    float uax = fminf(fmaxf(pax + 0.5f, 0.0f), HI);
    float uay = fminf(fmaxf(pay + 0.5f, 0.0f), HI);
    float uaz = fminf(fmaxf(paz + 0.5f, 0.0f), HI);
    float ubx = fminf(fmaxf(pbx + 0.5f, 0.0f), HI);
    float uby = fminf(fmaxf(pby + 0.5f, 0.0f), HI);
    float ubz = fminf(fmaxf(pbz + 0.5f, 0.0f), HI);

    // ---- density layer-1 accumulators for both points (init from bias) ----
    F2 accA[32], accB[32];
    {
        const ulonglong2* bb = reinterpret_cast<const ulonglong2*>(sw + OB1);
        #pragma unroll
        for (int j = 0; j < 16; ++j) {
            ulonglong2 b = bb[j];
            accA[2*j].u = b.x; accA[2*j+1].u = b.y;
            accB[2*j].u = b.x; accB[2*j+1].u = b.y;
        }
    }

    // ---- hash encode fused with layer-1 for both points ----
    const int NL[16] = {16, 22, 30, 42, 58, 80, 110, 152, 210, 290, 400, 552, 762, 1052, 1452, 2004};
    const float2* __restrict__ tab2 = reinterpret_cast<const float2*>(tables);

    #pragma unroll
    for (int L = 0; L < 16; ++L) {
        const float2* tb = tab2 + (size_t)L * TSZ;
        float fA0, fA1, fB0, fB1;
        // --- point A gathers + interp ---
        {
            float sx = uax * (float)NL[L], sy = uay * (float)NL[L], sz = uaz * (float)NL[L];
            float fx = floorf(sx), fy = floorf(sy), fz = floorf(sz);
            float tx = sx - fx, ty = sy - fy, tz = sz - fz;
            uint32_t xi0 = (uint32_t)fx, yi0 = (uint32_t)fy, zi0 = (uint32_t)fz;
            uint32_t xi1 = xi0 + 1u;
            uint32_t hy0 = yi0 * PI2, hy1 = hy0 + PI2;
            uint32_t hz0 = zi0 * PI3, hz1 = hz0 + PI3;
            float2 g0 = __ldg(tb + ((xi0 ^ hy0 ^ hz0) & TMASK));
            float2 g1 = __ldg(tb + ((xi1 ^ hy0 ^ hz0) & TMASK));
            float2 g2 = __ldg(tb + ((xi0 ^ hy1 ^ hz0) & TMASK));
            float2 g3 = __ldg(tb + ((xi1 ^ hy1 ^ hz0) & TMASK));
            float2 g4 = __ldg(tb + ((xi0 ^ hy0 ^ hz1) & TMASK));
            float2 g5 = __ldg(tb + ((xi1 ^ hy0 ^ hz1) & TMASK));
            float2 g6 = __ldg(tb + ((xi0 ^ hy1 ^ hz1) & TMASK));
            float2 g7 = __ldg(tb + ((xi1 ^ hy1 ^ hz1) & TMASK));
            float wx0 = 1.0f - tx, wy0 = 1.0f - ty, wz0 = 1.0f - tz;
            float w00 = wy0 * wz0, w10 = ty * wz0, w01 = wy0 * tz, w11 = ty * tz;
            float f0 = 0.0f, f1 = 0.0f, wgt;
            wgt = wx0 * w00; f0 = fmaf(wgt, g0.x, f0); f1 = fmaf(wgt, g0.y, f1);
            wgt = tx  * w00; f0 = fmaf(wgt, g1.x, f0); f1 = fmaf(wgt, g1.y, f1);
            wgt = wx0 * w10; f0 = fmaf(wgt, g2.x, f0); f1 = fmaf(wgt, g2.y, f1);
            wgt = tx  * w10; f0 = fmaf(wgt, g3.x, f0); f1 = fmaf(wgt, g3.y, f1);
            wgt = wx0 * w01; f0 = fmaf(wgt, g4.x, f0); f1 = fmaf(wgt, g4.y, f1);
            wgt = tx  * w01; f0 = fmaf(wgt, g5.x, f0); f1 = fmaf(wgt, g5.y, f1);
            wgt = wx0 * w11; f0 = fmaf(wgt, g6.x, f0); f1 = fmaf(wgt, g6.y, f1);
            wgt = tx  * w11; f0 = fmaf(wgt, g7.x, f0); f1 = fmaf(wgt, g7.y, f1);
            fA0 = f0; fA1 = f1;
        }
        // --- point B gathers + interp ---
        {
            float sx = ubx * (float)NL[L], sy = uby * (float)NL[L], sz = ubz * (float)NL[L];
            float fx = floorf(sx), fy = floorf(sy), fz = floorf(sz);
            float tx = sx - fx, ty = sy - fy, tz = sz - fz;
            uint32_t xi0 = (uint32_t)fx, yi0 = (uint32_t)fy, zi0 = (uint32_t)fz;
            uint32_t xi1 = xi0 + 1u;
            uint32_t hy0 = yi0 * PI2, hy1 = hy0 + PI2;
            uint32_t hz0 = zi0 * PI3, hz1 = hz0 + PI3;
            float2 g0 = __ldg(tb + ((xi0 ^ hy0 ^ hz0) & TMASK));
            float2 g1 = __ldg(tb + ((xi1 ^ hy0 ^ hz0) & TMASK));
            float2 g2 = __ldg(tb + ((xi0 ^ hy1 ^ hz0) & TMASK));
            float2 g3 = __ldg(tb + ((xi1 ^ hy1 ^ hz0) & TMASK));
            float2 g4 = __ldg(tb + ((xi0 ^ hy0 ^ hz1) & TMASK));
            float2 g5 = __ldg(tb + ((xi1 ^ hy0 ^ hz1) & TMASK));
            float2 g6 = __ldg(tb + ((xi0 ^ hy1 ^ hz1) & TMASK));
            float2 g7 = __ldg(tb + ((xi1 ^ hy1 ^ hz1) & TMASK));
            float wx0 = 1.0f - tx, wy0 = 1.0f - ty, wz0 = 1.0f - tz;
            float w00 = wy0 * wz0, w10 = ty * wz0, w01 = wy0 * tz, w11 = ty * tz;
            float f0 = 0.0f, f1 = 0.0f, wgt;
            wgt = wx0 * w00; f0 = fmaf(wgt, g0.x, f0); f1 = fmaf(wgt, g0.y, f1);
            wgt = tx  * w00; f0 = fmaf(wgt, g1.x, f0); f1 = fmaf(wgt, g1.y, f1);
            wgt = wx0 * w10; f0 = fmaf(wgt, g2.x, f0); f1 = fmaf(wgt, g2.y, f1);
            wgt = tx  * w10; f0 = fmaf(wgt, g3.x, f0); f1 = fmaf(wgt, g3.y, f1);
            wgt = wx0 * w01; f0 = fmaf(wgt, g4.x, f0); f1 = fmaf(wgt, g4.y, f1);
            wgt = tx  * w01; f0 = fmaf(wgt, g5.x, f0); f1 = fmaf(wgt, g5.y, f1);
            wgt = wx0 * w11; f0 = fmaf(wgt, g6.x, f0); f1 = fmaf(wgt, g6.y, f1);
            wgt = tx  * w11; f0 = fmaf(wgt, g7.x, f0); f1 = fmaf(wgt, g7.y, f1);
            fB0 = f0; fB1 = f1;
        }
        // fused layer-1 rows 2L, 2L+1 — weights loaded ONCE, used for both points
        ull a0 = bcast2(fA0), a1 = bcast2(fA1);
        ull b0 = bcast2(fB0), b1 = bcast2(fB1);
        const ulonglong2* wr0 = reinterpret_cast<const ulonglong2*>(sw + OW1 + (2*L)   * 64);
        const ulonglong2* wr1 = reinterpret_cast<const ulonglong2*>(sw + OW1 + (2*L+1) * 64);
        #pragma unroll
        for (int j = 0; j < 16; ++j) {
            ulonglong2 wa = wr0[j];
            fma2(accA[2*j].u,   a0, wa.x); fma2(accA[2*j+1].u, a0, wa.y);
            fma2(accB[2*j].u,   b0, wa.x); fma2(accB[2*j+1].u, b0, wa.y);
            ulonglong2 wb = wr1[j];
            fma2(accA[2*j].u,   a1, wb.x); fma2(accA[2*j+1].u, a1, wb.y);
            fma2(accB[2*j].u,   b1, wb.x); fma2(accB[2*j+1].u, b1, wb.y);
        }
    }
    #pragma unroll
    for (int j = 0; j < 32; ++j) {
        accA[j].f.x = fmaxf(accA[j].f.x, 0.0f); accA[j].f.y = fmaxf(accA[j].f.y, 0.0f);
        accB[j].f.x = fmaxf(accB[j].f.x, 0.0f); accB[j].f.y = fmaxf(accB[j].f.y, 0.0f);
    }

    // ---- density layer 2: 64 -> 16 (no activation), both points ----
    F2 h2A[8], h2B[8];
    {
        const ulonglong2* bb = reinterpret_cast<const ulonglong2*>(sw + OB2);
        #pragma unroll
        for (int j = 0; j < 4; ++j) {
            ulonglong2 b = bb[j];
            h2A[2*j].u = b.x; h2A[2*j+1].u = b.y;
            h2B[2*j].u = b.x; h2B[2*j+1].u = b.y;
        }
        #pragma unroll
        for (int i = 0; i < 64; ++i) {
            float aA = (i & 1) ? accA[i >> 1].f.y : accA[i >> 1].f.x;
            float aB = (i & 1) ? accB[i >> 1].f.y : accB[i >> 1].f.x;
            ull a2 = bcast2(aA), b2 = bcast2(aB);
            const ulonglong2* wr = reinterpret_cast<const ulonglong2*>(sw + OW2 + i * 16);
            #pragma unroll
            for (int j = 0; j < 4; ++j) {
                ulonglong2 w = wr[j];
                fma2(h2A[2*j].u, a2, w.x); fma2(h2A[2*j+1].u, a2, w.y);
                fma2(h2B[2*j].u, b2, w.x); fma2(h2B[2*j+1].u, b2, w.y);
            }
        }
    }
    float sigA = h2A[0].f.x, sigB = h2B[0].f.x;

    // ---- direction components ----
    float dA[3], dB[3];
    dA[0] = dirs[lA * 3 + 0]; dA[1] = dirs[lA * 3 + 1]; dA[2] = dirs[lA * 3 + 2];
    dB[0] = dirs[lB * 3 + 0]; dB[1] = dirs[lB * 3 + 1]; dB[2] = dirs[lB * 3 + 2];

    // ---- color layer 1: 43 -> 64, relu; 2 x 32-output halves, both points ----
    // reuse accA/accB as acc3 storage
    #pragma unroll
    for (int h = 0; h < 2; ++h) {
        F2 a3A[16], a3B[16];
        {
            const ulonglong2* bb = reinterpret_cast<const ulonglong2*>(sw + OB3 + h * 32);
            #pragma unroll
            for (int j = 0; j < 8; ++j) {
                ulonglong2 b = bb[j];
                a3A[2*j].u = b.x; a3A[2*j+1].u = b.y;
                a3B[2*j].u = b.x; a3B[2*j+1].u = b.y;
            }
        }
        // rows 0..2: raw direction
        #pragma unroll
        for (int c = 0; c < 3; ++c) {
            ull aA = bcast2(dA[c]), aB = bcast2(dB[c]);
            const ulonglong2* wr = reinterpret_cast<const ulonglong2*>(sw + OW3 + c * 64 + h * 32);
            #pragma unroll
            for (int j = 0; j < 8; ++j) {
                ulonglong2 w = wr[j];
                fma2(a3A[2*j].u, aA, w.x); fma2(a3A[2*j+1].u, aA, w.y);
                fma2(a3B[2*j].u, aB, w.x); fma2(a3B[2*j+1].u, aB, w.y);
            }
        }
        // rows 3..14 sin, 15..26 cos (MUFU recompute)
        #pragma unroll
        for (int c = 0; c < 3; ++c) {
            #pragma unroll
            for (int f = 0; f < 4; ++f) {
                float angA = dA[c] * (float)(1 << f);
                float angB = dB[c] * (float)(1 << f);
                ull sA = bcast2(__sinf(angA)), sB = bcast2(__sinf(angB));
                const ulonglong2* wrs = reinterpret_cast<const ulonglong2*>(sw + OW3 + (3 + c*4 + f) * 64 + h * 32);
                #pragma unroll
                for (int j = 0; j < 8; ++j) {
                    ulonglong2 w = wrs[j];
                    fma2(a3A[2*j].u, sA, w.x); fma2(a3A[2*j+1].u, sA, w.y);
                    fma2(a3B[2*j].u, sB, w.x); fma2(a3B[2*j+1].u, sB, w.y);
                }
                ull cA = bcast2(__cosf(angA)), cB = bcast2(__cosf(angB));
                const ulonglong2* wrc = reinterpret_cast<const ulonglong2*>(sw + OW3 + (15 + c*4 + f) * 64 + h * 32);
                #pragma unroll
                for (int j = 0; j < 8; ++j) {
                    ulonglong2 w = wrc[j];
                    fma2(a3A[2*j].u, cA, w.x); fma2(a3A[2*j+1].u, cA, w.y);
                    fma2(a3B[2*j].u, cB, w.x); fma2(a3B[2*j+1].u, cB, w.y);
                }
            }
        }
        // rows 27..42: density features (h2)
        #pragma unroll
        for (int r = 0; r < 16; ++r) {
            float aA = (r & 1) ? h2A[r >> 1].f.y : h2A[r >> 1].f.x;
            float aB = (r & 1) ? h2B[r >> 1].f.y : h2B[r >> 1].f.x;
            ull a2 = bcast2(aA), b2 = bcast2(aB);
            const ulonglong2* wr = reinterpret_cast<const ulonglong2*>(sw + OW3 + (27 + r) * 64 + h * 32);
            #pragma unroll
            for (int j = 0; j < 8; ++j) {
                ulonglong2 w = wr[j];
                fma2(a3A[2*j].u, a2, w.x); fma2(a3A[2*j+1].u, a2, w.y);
                fma2(a3B[2*j].u, b2, w.x); fma2(a3B[2*j+1].u, b2, w.y);
            }
        }
        #pragma unroll
        for (int j = 0; j < 16; ++j) {
            a3A[j].f.x = fmaxf(a3A[j].f.x, 0.0f); a3A[j].f.y = fmaxf(a3A[j].f.y, 0.0f);
            a3B[j].f.x = fmaxf(a3B[j].f.x, 0.0f); a3B[j].f.y = fmaxf(a3B[j].f.y, 0.0f);
            accA[h * 16 + j] = a3A[j];
            accB[h * 16 + j] = a3B[j];
        }
    }

    // ---- color layer 2 (64->64, relu) fused with layer 3 (64->3), both points ----
    ull vA2[3] = {0, 0, 0}, vB2[3] = {0, 0, 0};
    #pragma unroll
    for (int h = 0; h < 2; ++h) {
        F2 a4A[16], a4B[16];
        {
            const ulonglong2* bb = reinterpret_cast<const ulonglong2*>(sw + OB4 + h * 32);
            #pragma unroll
            for (int j = 0; j < 8; ++j) {
                ulonglong2 b = bb[j];
                a4A[2*j].u = b.x; a4A[2*j+1].u = b.y;
                a4B[2*j].u = b.x; a4B[2*j+1].u = b.y;
            }
        }
        #pragma unroll
        for (int i = 0; i < 64; ++i) {
            float aA = (i & 1) ? accA[i >> 1].f.y : accA[i >> 1].f.x;
            float aB = (i & 1) ? accB[i >> 1].f.y : accB[i >> 1].f.x;
            ull a2 = bcast2(aA), b2 = bcast2(aB);
            const ulonglong2* wr = reinterpret_cast<const ulonglong2*>(sw + OW4 + i * 64 + h * 32);
            #pragma unroll
            for (int j = 0; j < 8; ++j) {
                ulonglong2 w = wr[j];
                fma2(a4A[2*j].u, a2, w.x); fma2(a4A[2*j+1].u, a2, w.y);
                fma2(a4B[2*j].u, b2, w.x); fma2(a4B[2*j+1].u, b2, w.y);
            }
        }
        #pragma unroll
        for (int j = 0; j < 16; ++j) {
            a4A[j].f.x = fmaxf(a4A[j].f.x, 0.0f); a4A[j].f.y = fmaxf(a4A[j].f.y, 0.0f);
            a4B[j].f.x = fmaxf(a4B[j].f.x, 0.0f); a4B[j].f.y = fmaxf(a4B[j].f.y, 0.0f);
        }
        #pragma unroll
        for (int c = 0; c < 3; ++c) {
            const ulonglong2* wr5 = reinterpret_cast<const ulonglong2*>(sw + OW5T + c * 64 + h * 32);
            #pragma unroll
            for (int j = 0; j < 8; ++j) {
                ulonglong2 w = wr5[j];
                fma2(vA2[c], a4A[2*j].u, w.x); fma2(vA2[c], a4A[2*j+1].u, w.y);
                fma2(vB2[c], a4B[2*j].u, w.x); fma2(vB2[c], a4B[2*j+1].u, w.y);
            }
        }
    }

    float colA[3], colB[3];
    #pragma unroll
    for (int c = 0; c < 3; ++c) {
        F2 ta; ta.u = vA2[c];
        F2 tb; tb.u = vB2[c];
        float va = ta.f.x + ta.f.y + sw[OB5 + c];
        float vb = tb.f.x + tb.f.y + sw[OB5 + c];
        colA[c] = inA ? 1.0f / (1.0f + __expf(-va)) : 0.0f;
        colB[c] = inB ? 1.0f / (1.0f + __expf(-vb)) : 0.0f;
    }

    // ---- outputs: [N,3] color then [N] log_sigma ----
    if (vA) {
        out[giA * 3 + 0] = colA[0];
        out[giA * 3 + 1] = colA[1];
        out[giA * 3 + 2] = colA[2];
        out[(size_t)3 * n + giA] = inA ? sigA : -100000.0f;
    }
    if (vB) {
        out[giB * 3 + 0] = colB[0];
        out[giB * 3 + 1] = colB[1];
        out[giB * 3 + 2] = colB[2];
        out[(size_t)3 * n + giB] = inB ? sigB : -100000.0f;
    }
}

extern "C" void kernel_launch(void* const* d_in, const int* in_sizes, int n_in,
                              void* d_out, int out_size) {
    const float* x      = (const float*)d_in[0];
    const float* d      = (const float*)d_in[1];
    const float* tables = (const float*)d_in[2];
    const float* w1 = (const float*)d_in[3];
    const float* b1 = (const float*)d_in[4];
    const float* w2 = (const float*)d_in[5];
    const float* b2 = (const float*)d_in[6];
    const float* w3 = (const float*)d_in[7];
    const float* b3 = (const float*)d_in[8];
    const float* w4 = (const float*)d_in[9];
    const float* b4 = (const float*)d_in[10];
    const float* w5 = (const float*)d_in[11];
    const float* b5 = (const float*)d_in[12];
    float* out = (float*)d_out;

    int n = in_sizes[0] / 3;
    int blocks = (n + 255) / 256;
    ngp_kernel<<<blocks, 128>>>(x, d, tables, w1, b1, w2, b2, w3, b3, w4, b4, w5, b5, out, n);
}

// round 6
// speedup vs baseline: 2.5000x; 2.5000x over previous
#include <cuda_runtime.h>
#include <stdint.h>
#include <math.h>

typedef unsigned long long ull;

#define TSZ   524288u
#define TMASK 524287u
#define PI2   2654435761u
#define PI3   805459861u

// __constant__ weights for the two big color layers (W3: 43x64, W4: 64x64)
#define CW3_ULL 1376          // 2752 floats
#define CW4_ULL 2048          // 4096 floats
__constant__ ull cW34[CW3_ULL + CW4_ULL];   // 27.4 KB

// shared-memory float offsets (W3/W4 removed; all row starts 16B-aligned)
#define OW1 0       // [32,64]
#define OB1 2048    // [64]
#define OW2 2112    // [64,16]
#define OB2 3136    // [16]
#define OB3 3152    // [64]
#define OB4 3216    // [64]
#define OW5T 3280   // [3,64] transposed
#define OB5 3472    // [3] (+1 pad)
#define SW_TOTAL 3476

__device__ __forceinline__ void fma2(ull &c, ull a, ull b) {
    asm("fma.rn.f32x2 %0, %1, %2, %0;" : "+l"(c) : "l"(a), "l"(b));
}
__device__ __forceinline__ ull bcast2(float a) {
    ull r; asm("mov.b64 %0, {%1, %1};" : "=l"(r) : "f"(a), "f"(a)); return r;
}

union F2 { float2 f; ull u; };

__global__ __launch_bounds__(128, 4) void ngp_kernel(
    const float* __restrict__ x, const float* __restrict__ dirs,
    const float* __restrict__ tables,
    const float* __restrict__ w1, const float* __restrict__ b1,
    const float* __restrict__ w2, const float* __restrict__ b2,
    const float* __restrict__ b3,
    const float* __restrict__ b4,
    const float* __restrict__ w5, const float* __restrict__ b5,
    float* __restrict__ out, int n)
{
    __shared__ __align__(16) float sw[SW_TOTAL];
    const int tid = threadIdx.x;

    // cooperative weight staging (coalesced; sources L2-resident)
    for (int t = tid; t < 2048; t += 128) sw[OW1 + t] = w1[t];
    for (int t = tid; t < 64;   t += 128) sw[OB1 + t] = b1[t];
    for (int t = tid; t < 1024; t += 128) sw[OW2 + t] = w2[t];
    for (int t = tid; t < 16;   t += 128) sw[OB2 + t] = b2[t];
    for (int t = tid; t < 64;   t += 128) sw[OB3 + t] = b3[t];
    for (int t = tid; t < 64;   t += 128) sw[OB4 + t] = b4[t];
    for (int t = tid; t < 192;  t += 128) sw[OW5T + (t % 3) * 64 + (t / 3)] = w5[t];  // transpose
    if (tid < 3) sw[OB5 + tid] = b5[tid];
    __syncthreads();

    const int gi = blockIdx.x * 128 + tid;
    if (gi >= n) return;

    // ---- position, AABB mask, normalization ----
    float px = x[gi * 3 + 0] / 3.0f;
    float py = x[gi * 3 + 1] / 3.0f;
    float pz = x[gi * 3 + 2] / 3.0f;
    bool inside = (fabsf(px) < 0.5f) && (fabsf(py) < 0.5f) && (fabsf(pz) < 0.5f);
    const float HI = 1.0f - 1e-7f;
    float ux = fminf(fmaxf(px + 0.5f, 0.0f), HI);
    float uy = fminf(fmaxf(py + 0.5f, 0.0f), HI);
    float uz = fminf(fmaxf(pz + 0.5f, 0.0f), HI);

    // ---- density layer-1 accumulators (init from bias; encode fused below) ----
    F2 acc1[32];
    {
        const ulonglong2* bb = reinterpret_cast<const ulonglong2*>(sw + OB1);
        #pragma unroll
        for (int j = 0; j < 16; ++j) { acc1[2*j].u = bb[j].x; acc1[2*j+1].u = bb[j].y; }
    }

    // ---- multiresolution hash encode, fused with layer-1 accumulation ----
    const int NL[16] = {16, 22, 30, 42, 58, 80, 110, 152, 210, 290, 400, 552, 762, 1052, 1452, 2004};
    const float2* __restrict__ tab2 = reinterpret_cast<const float2*>(tables);

    #pragma unroll
    for (int L = 0; L < 16; ++L) {
        float sx = ux * (float)NL[L];
        float sy = uy * (float)NL[L];
        float sz = uz * (float)NL[L];
        float fx = floorf(sx), fy = floorf(sy), fz = floorf(sz);
        float tx = sx - fx,    ty = sy - fy,    tz = sz - fz;
        uint32_t xi0 = (uint32_t)fx, yi0 = (uint32_t)fy, zi0 = (uint32_t)fz;
        uint32_t xi1 = xi0 + 1u;
        uint32_t hy0 = yi0 * PI2, hy1 = hy0 + PI2;
        uint32_t hz0 = zi0 * PI3, hz1 = hz0 + PI3;

        const float2* tb = tab2 + (size_t)L * TSZ;
        float2 g0 = __ldg(tb + ((xi0 ^ hy0 ^ hz0) & TMASK));
        float2 g1 = __ldg(tb + ((xi1 ^ hy0 ^ hz0) & TMASK));
        float2 g2 = __ldg(tb + ((xi0 ^ hy1 ^ hz0) & TMASK));
        float2 g3 = __ldg(tb + ((xi1 ^ hy1 ^ hz0) & TMASK));
        float2 g4 = __ldg(tb + ((xi0 ^ hy0 ^ hz1) & TMASK));
        float2 g5 = __ldg(tb + ((xi1 ^ hy0 ^ hz1) & TMASK));
        float2 g6 = __ldg(tb + ((xi0 ^ hy1 ^ hz1) & TMASK));
        float2 g7 = __ldg(tb + ((xi1 ^ hy1 ^ hz1) & TMASK));

        float wx0 = 1.0f - tx, wy0 = 1.0f - ty, wz0 = 1.0f - tz;
        float w00 = wy0 * wz0, w10 = ty * wz0, w01 = wy0 * tz, w11 = ty * tz;

        float f0 = 0.0f, f1 = 0.0f, wgt;
        wgt = wx0 * w00; f0 = fmaf(wgt, g0.x, f0); f1 = fmaf(wgt, g0.y, f1);
        wgt = tx  * w00; f0 = fmaf(wgt, g1.x, f0); f1 = fmaf(wgt, g1.y, f1);
        wgt = wx0 * w10; f0 = fmaf(wgt, g2.x, f0); f1 = fmaf(wgt, g2.y, f1);
        wgt = tx  * w10; f0 = fmaf(wgt, g3.x, f0); f1 = fmaf(wgt, g3.y, f1);
        wgt = wx0 * w01; f0 = fmaf(wgt, g4.x, f0); f1 = fmaf(wgt, g4.y, f1);
        wgt = tx  * w01; f0 = fmaf(wgt, g5.x, f0); f1 = fmaf(wgt, g5.y, f1);
        wgt = wx0 * w11; f0 = fmaf(wgt, g6.x, f0); f1 = fmaf(wgt, g6.y, f1);
        wgt = tx  * w11; f0 = fmaf(wgt, g7.x, f0); f1 = fmaf(wgt, g7.y, f1);

        // fused layer-1 rows 2L, 2L+1 (LDS.128: 2 packed operand pairs per load)
        ull a0 = bcast2(f0), a1 = bcast2(f1);
        const ulonglong2* wr0 = reinterpret_cast<const ulonglong2*>(sw + OW1 + (2*L)   * 64);
        const ulonglong2* wr1 = reinterpret_cast<const ulonglong2*>(sw + OW1 + (2*L+1) * 64);
        #pragma unroll
        for (int j = 0; j < 16; ++j) {
            ulonglong2 wa = wr0[j];
            fma2(acc1[2*j].u,   a0, wa.x);
            fma2(acc1[2*j+1].u, a0, wa.y);
            ulonglong2 wb = wr1[j];
            fma2(acc1[2*j].u,   a1, wb.x);
            fma2(acc1[2*j+1].u, a1, wb.y);
        }
    }
    #pragma unroll
    for (int j = 0; j < 32; ++j) {
        acc1[j].f.x = fmaxf(acc1[j].f.x, 0.0f);
        acc1[j].f.y = fmaxf(acc1[j].f.y, 0.0f);
    }

    // ---- density layer 2: 64 -> 16 (no activation) ----
    F2 acc2[8];
    {
        const ulonglong2* bb = reinterpret_cast<const ulonglong2*>(sw + OB2);
        #pragma unroll
        for (int j = 0; j < 4; ++j) { acc2[2*j].u = bb[j].x; acc2[2*j+1].u = bb[j].y; }
        #pragma unroll
        for (int i = 0; i < 64; ++i) {
            float a = (i & 1) ? acc1[i >> 1].f.y : acc1[i >> 1].f.x;
            ull a2 = bcast2(a);
            const ulonglong2* wr = reinterpret_cast<const ulonglong2*>(sw + OW2 + i * 16);
            #pragma unroll
            for (int j = 0; j < 4; ++j) {
                ulonglong2 w = wr[j];
                fma2(acc2[2*j].u,   a2, w.x);
                fma2(acc2[2*j+1].u, a2, w.y);
            }
        }
    }
    float sigma_raw = acc2[0].f.x;

    // ---- direction components ----
    float dcv[3];
    dcv[0] = dirs[gi * 3 + 0];
    dcv[1] = dirs[gi * 3 + 1];
    dcv[2] = dirs[gi * 3 + 2];

    // ---- color layer 1: 43 -> 64, relu. Weights from __constant__ (uniform path).
    //      2 x 32-output halves; trig recomputed per half (MUFU). ----
    F2 acc3[32];
    #pragma unroll
    for (int h = 0; h < 2; ++h) {
        F2 a3[16];
        {
            const ulonglong2* bb = reinterpret_cast<const ulonglong2*>(sw + OB3 + h * 32);
            #pragma unroll
            for (int j = 0; j < 8; ++j) { a3[2*j].u = bb[j].x; a3[2*j+1].u = bb[j].y; }
        }
        // rows 0..2: raw direction
        #pragma unroll
        for (int c = 0; c < 3; ++c) {
            ull a2v = bcast2(dcv[c]);
            const ull* wr = cW34 + c * 32 + h * 16;
            #pragma unroll
            for (int j = 0; j < 8; ++j) {
                fma2(a3[2*j].u,   a2v, wr[2*j]);
                fma2(a3[2*j+1].u, a2v, wr[2*j+1]);
            }
        }
        // rows 3..14 sin, 15..26 cos (computed on the fly)
        #pragma unroll
        for (int c = 0; c < 3; ++c) {
            #pragma unroll
            for (int f = 0; f < 4; ++f) {
                float ang = dcv[c] * (float)(1 << f);
                ull s2 = bcast2(__sinf(ang));
                const ull* wrs = cW34 + (3 + c*4 + f) * 32 + h * 16;
                #pragma unroll
                for (int j = 0; j < 8; ++j) {
                    fma2(a3[2*j].u,   s2, wrs[2*j]);
                    fma2(a3[2*j+1].u, s2, wrs[2*j+1]);
                }
                ull c2 = bcast2(__cosf(ang));
                const ull* wrc = cW34 + (15 + c*4 + f) * 32 + h * 16;
                #pragma unroll
                for (int j = 0; j < 8; ++j) {
                    fma2(a3[2*j].u,   c2, wrc[2*j]);
                    fma2(a3[2*j+1].u, c2, wrc[2*j+1]);
                }
            }
        }
        // rows 27..42: density features (acc2)
        #pragma unroll
        for (int r = 0; r < 16; ++r) {
            float a = (r & 1) ? acc2[r >> 1].f.y : acc2[r >> 1].f.x;
            ull a2v = bcast2(a);
            const ull* wr = cW34 + (27 + r) * 32 + h * 16;
            #pragma unroll
            for (int j = 0; j < 8; ++j) {
                fma2(a3[2*j].u,   a2v, wr[2*j]);
                fma2(a3[2*j+1].u, a2v, wr[2*j+1]);
            }
        }
        #pragma unroll
        for (int j = 0; j < 16; ++j) {
            a3[j].f.x = fmaxf(a3[j].f.x, 0.0f);
            a3[j].f.y = fmaxf(a3[j].f.y, 0.0f);
            acc3[h * 16 + j] = a3[j];
        }
    }

    // ---- color layer 2 (64->64, relu) fused with layer 3 (64->3):
    //      weights from __constant__; 2 x 32-output halves consumed into vc. ----
    ull vr2 = 0, vg2 = 0, vb2 = 0;
    #pragma unroll
    for (int h = 0; h < 2; ++h) {
        F2 a4[16];
        {
            const ulonglong2* bb = reinterpret_cast<const ulonglong2*>(sw + OB4 + h * 32);
            #pragma unroll
            for (int j = 0; j < 8; ++j) { a4[2*j].u = bb[j].x; a4[2*j+1].u = bb[j].y; }
        }
        #pragma unroll
        for (int i = 0; i < 64; ++i) {
            float a = (i & 1) ? acc3[i >> 1].f.y : acc3[i >> 1].f.x;
            ull a2v = bcast2(a);
            const ull* wr = cW34 + CW3_ULL + i * 32 + h * 16;
            #pragma unroll
            for (int j = 0; j < 8; ++j) {
                fma2(a4[2*j].u,   a2v, wr[2*j]);
                fma2(a4[2*j+1].u, a2v, wr[2*j+1]);
            }
        }
        #pragma unroll
        for (int j = 0; j < 16; ++j) {
            a4[j].f.x = fmaxf(a4[j].f.x, 0.0f);
            a4[j].f.y = fmaxf(a4[j].f.y, 0.0f);
        }
        // layer-5 partial dot: outputs [h*32, h*32+32)
        const ulonglong2* wr5r = reinterpret_cast<const ulonglong2*>(sw + OW5T + 0 * 64 + h * 32);
        const ulonglong2* wr5g = reinterpret_cast<const ulonglong2*>(sw + OW5T + 1 * 64 + h * 32);
        const ulonglong2* wr5b = reinterpret_cast<const ulonglong2*>(sw + OW5T + 2 * 64 + h * 32);
        #pragma unroll
        for (int j = 0; j < 8; ++j) {
            ulonglong2 wr_ = wr5r[j];
            fma2(vr2, a4[2*j].u, wr_.x);
            fma2(vr2, a4[2*j+1].u, wr_.y);
            ulonglong2 wg_ = wr5g[j];
            fma2(vg2, a4[2*j].u, wg_.x);
            fma2(vg2, a4[2*j+1].u, wg_.y);
            ulonglong2 wb_ = wr5b[j];
            fma2(vb2, a4[2*j].u, wb_.x);
            fma2(vb2, a4[2*j+1].u, wb_.y);
        }
    }
    F2 tr; tr.u = vr2;
    F2 tg; tg.u = vg2;
    F2 tb_; tb_.u = vb2;
    float vr = tr.f.x + tr.f.y + sw[OB5 + 0];
    float vg = tg.f.x + tg.f.y + sw[OB5 + 1];
    float vb = tb_.f.x + tb_.f.y + sw[OB5 + 2];

    float cr = inside ? 1.0f / (1.0f + __expf(-vr)) : 0.0f;
    float cg = inside ? 1.0f / (1.0f + __expf(-vg)) : 0.0f;
    float cb = inside ? 1.0f / (1.0f + __expf(-vb)) : 0.0f;

    // ---- outputs: [N,3] color then [N] log_sigma ----
    out[gi * 3 + 0] = cr;
    out[gi * 3 + 1] = cg;
    out[gi * 3 + 2] = cb;
    out[(size_t)3 * n + gi] = inside ? sigma_raw : -100000.0f;
}

extern "C" void kernel_launch(void* const* d_in, const int* in_sizes, int n_in,
                              void* d_out, int out_size) {
    const float* x      = (const float*)d_in[0];
    const float* d      = (const float*)d_in[1];
    const float* tables = (const float*)d_in[2];
    const float* w1 = (const float*)d_in[3];
    const float* b1 = (const float*)d_in[4];
    const float* w2 = (const float*)d_in[5];
    const float* b2 = (const float*)d_in[6];
    const float* w3 = (const float*)d_in[7];
    const float* b3 = (const float*)d_in[8];
    const float* w4 = (const float*)d_in[9];
    const float* b4 = (const float*)d_in[10];
    const float* w5 = (const float*)d_in[11];
    const float* b5 = (const float*)d_in[12];
    float* out = (float*)d_out;

    // stage W3 and W4 into constant memory (device-to-device, graph-capturable)
    cudaMemcpyToSymbolAsync(cW34, w3, 2752 * sizeof(float), 0, cudaMemcpyDeviceToDevice, 0);
    cudaMemcpyToSymbolAsync(cW34, w4, 4096 * sizeof(float), CW3_ULL * sizeof(ull), cudaMemcpyDeviceToDevice, 0);

    int n = in_sizes[0] / 3;
    int blocks = (n + 127) / 128;
    ngp_kernel<<<blocks, 128>>>(x, d, tables, w1, b1, w2, b2, b3, b4, w5, b5, out, n);
}

// round 8
// speedup vs baseline: 2.7432x; 1.0973x over previous
#include <cuda_runtime.h>
#include <stdint.h>
#include <math.h>

typedef unsigned long long ull;

#define TSZ   524288u
#define TMASK 524287u
#define PI2   2654435761u
#define PI3   805459861u

// __constant__ weights: W3 (43x64) fully + W4 rows 0..45
#define CW3_ULL 1376          // 2752 floats
#define CW4_ULL 2048          // 4096 floats (full W4 copied; rows 46+ unused)
__constant__ ull cW34[CW3_ULL + CW4_ULL];
#define W4_CONST_ROWS 46

// shared-memory float offsets (16B-aligned rows)
#define OW1  0      // [32,64]
#define OB1  2048   // [64]
#define OW2  2112   // [64,16]
#define OB2  3136   // [16]
#define OB3  3152   // [64]
#define OB4  3216   // [64]
#define OW4S 3280   // W4 rows 46..63: [18,64]
#define OW5T 4432   // [3,64] transposed
#define OB5  4624   // [3] (+1 pad)
#define SW_TOTAL 4628

__device__ __forceinline__ void fma2(ull &c, ull a, ull b) {
    asm("fma.rn.f32x2 %0, %1, %2, %0;" : "+l"(c) : "l"(a), "l"(b));
}
__device__ __forceinline__ ull bcast2(float a) {
    ull r; asm("mov.b64 %0, {%1, %1};" : "=l"(r) : "f"(a), "f"(a)); return r;
}

union F2 { float2 f; ull u; };

__global__ __launch_bounds__(128, 4) void ngp_kernel(
    const float* __restrict__ x, const float* __restrict__ dirs,
    const float* __restrict__ tables,
    const float* __restrict__ w1, const float* __restrict__ b1,
    const float* __restrict__ w2, const float* __restrict__ b2,
    const float* __restrict__ b3,
    const float* __restrict__ w4, const float* __restrict__ b4,
    const float* __restrict__ w5, const float* __restrict__ b5,
    float* __restrict__ out, int n)
{
    __shared__ __align__(16) float sw[SW_TOTAL];
    const int tid = threadIdx.x;

    // cooperative weight staging (coalesced; sources L2-resident)
    for (int t = tid; t < 2048; t += 128) sw[OW1 + t] = w1[t];
    for (int t = tid; t < 64;   t += 128) sw[OB1 + t] = b1[t];
    for (int t = tid; t < 1024; t += 128) sw[OW2 + t] = w2[t];
    for (int t = tid; t < 16;   t += 128) sw[OB2 + t] = b2[t];
    for (int t = tid; t < 64;   t += 128) sw[OB3 + t] = b3[t];
    for (int t = tid; t < 64;   t += 128) sw[OB4 + t] = b4[t];
    for (int t = tid; t < 1152; t += 128) sw[OW4S + t] = w4[W4_CONST_ROWS * 64 + t];
    for (int t = tid; t < 192;  t += 128) sw[OW5T + (t % 3) * 64 + (t / 3)] = w5[t];  // transpose
    if (tid < 3) sw[OB5 + tid] = b5[tid];
    __syncthreads();

    const int gi = blockIdx.x * 128 + tid;
    if (gi >= n) return;

    // ---- position, AABB mask, normalization ----
    float px = x[gi * 3 + 0] / 3.0f;
    float py = x[gi * 3 + 1] / 3.0f;
    float pz = x[gi * 3 + 2] / 3.0f;
    bool inside = (fabsf(px) < 0.5f) && (fabsf(py) < 0.5f) && (fabsf(pz) < 0.5f);
    const float HI = 1.0f - 1e-7f;
    float ux = fminf(fmaxf(px + 0.5f, 0.0f), HI);
    float uy = fminf(fmaxf(py + 0.5f, 0.0f), HI);
    float uz = fminf(fmaxf(pz + 0.5f, 0.0f), HI);

    // ---- density layer-1 accumulators (init from bias; encode fused below) ----
    F2 acc1[32];
    {
        const ulonglong2* bb = reinterpret_cast<const ulonglong2*>(sw + OB1);
        #pragma unroll
        for (int j = 0; j < 16; ++j) { acc1[2*j].u = bb[j].x; acc1[2*j+1].u = bb[j].y; }
    }

    // ---- multiresolution hash encode, fused with layer-1 accumulation ----
    const int NL[16] = {16, 22, 30, 42, 58, 80, 110, 152, 210, 290, 400, 552, 762, 1052, 1452, 2004};
    const float2* __restrict__ tab2 = reinterpret_cast<const float2*>(tables);

    #pragma unroll
    for (int L = 0; L < 16; ++L) {
        float sx = ux * (float)NL[L];
        float sy = uy * (float)NL[L];
        float sz = uz * (float)NL[L];
        float fx = floorf(sx), fy = floorf(sy), fz = floorf(sz);
        float tx = sx - fx,    ty = sy - fy,    tz = sz - fz;
        uint32_t xi0 = (uint32_t)fx, yi0 = (uint32_t)fy, zi0 = (uint32_t)fz;
        uint32_t xi1 = xi0 + 1u;
        uint32_t hy0 = yi0 * PI2, hy1 = hy0 + PI2;
        uint32_t hz0 = zi0 * PI3, hz1 = hz0 + PI3;

        const float2* tb = tab2 + (size_t)L * TSZ;
        float2 g0 = __ldg(tb + ((xi0 ^ hy0 ^ hz0) & TMASK));
        float2 g1 = __ldg(tb + ((xi1 ^ hy0 ^ hz0) & TMASK));
        float2 g2 = __ldg(tb + ((xi0 ^ hy1 ^ hz0) & TMASK));
        float2 g3 = __ldg(tb + ((xi1 ^ hy1 ^ hz0) & TMASK));
        float2 g4 = __ldg(tb + ((xi0 ^ hy0 ^ hz1) & TMASK));
        float2 g5 = __ldg(tb + ((xi1 ^ hy0 ^ hz1) & TMASK));
        float2 g6 = __ldg(tb + ((xi0 ^ hy1 ^ hz1) & TMASK));
        float2 g7 = __ldg(tb + ((xi1 ^ hy1 ^ hz1) & TMASK));

        float wx0 = 1.0f - tx, wy0 = 1.0f - ty, wz0 = 1.0f - tz;
        float w00 = wy0 * wz0, w10 = ty * wz0, w01 = wy0 * tz, w11 = ty * tz;

        float f0 = 0.0f, f1 = 0.0f, wgt;
        wgt = wx0 * w00; f0 = fmaf(wgt, g0.x, f0); f1 = fmaf(wgt, g0.y, f1);
        wgt = tx  * w00; f0 = fmaf(wgt, g1.x, f0); f1 = fmaf(wgt, g1.y, f1);
        wgt = wx0 * w10; f0 = fmaf(wgt, g2.x, f0); f1 = fmaf(wgt, g2.y, f1);
        wgt = tx  * w10; f0 = fmaf(wgt, g3.x, f0); f1 = fmaf(wgt, g3.y, f1);
        wgt = wx0 * w01; f0 = fmaf(wgt, g4.x, f0); f1 = fmaf(wgt, g4.y, f1);
        wgt = tx  * w01; f0 = fmaf(wgt, g5.x, f0); f1 = fmaf(wgt, g5.y, f1);
        wgt = wx0 * w11; f0 = fmaf(wgt, g6.x, f0); f1 = fmaf(wgt, g6.y, f1);
        wgt = tx  * w11; f0 = fmaf(wgt, g7.x, f0); f1 = fmaf(wgt, g7.y, f1);

        // fused layer-1 rows 2L, 2L+1 (LDS.128: 2 packed operand pairs per load)
        ull a0 = bcast2(f0), a1 = bcast2(f1);
        const ulonglong2* wr0 = reinterpret_cast<const ulonglong2*>(sw + OW1 + (2*L)   * 64);
        const ulonglong2* wr1 = reinterpret_cast<const ulonglong2*>(sw + OW1 + (2*L+1) * 64);
        #pragma unroll
        for (int j = 0; j < 16; ++j) {
            ulonglong2 wa = wr0[j];
            fma2(acc1[2*j].u,   a0, wa.x);
            fma2(acc1[2*j+1].u, a0, wa.y);
            ulonglong2 wb = wr1[j];
            fma2(acc1[2*j].u,   a1, wb.x);
            fma2(acc1[2*j+1].u, a1, wb.y);
        }
    }
    #pragma unroll
    for (int j = 0; j < 32; ++j) {
        acc1[j].f.x = fmaxf(acc1[j].f.x, 0.0f);
        acc1[j].f.y = fmaxf(acc1[j].f.y, 0.0f);
    }

    // ---- density layer 2: 64 -> 16 (no activation) ----
    F2 acc2[8];
    {
        const ulonglong2* bb = reinterpret_cast<const ulonglong2*>(sw + OB2);
        #pragma unroll
        for (int j = 0; j < 4; ++j) { acc2[2*j].u = bb[j].x; acc2[2*j+1].u = bb[j].y; }
        #pragma unroll
        for (int i = 0; i < 64; ++i) {
            float a = (i & 1) ? acc1[i >> 1].f.y : acc1[i >> 1].f.x;
            ull a2 = bcast2(a);
            const ulonglong2* wr = reinterpret_cast<const ulonglong2*>(sw + OW2 + i * 16);
            #pragma unroll
            for (int j = 0; j < 4; ++j) {
                ulonglong2 w = wr[j];
                fma2(acc2[2*j].u,   a2, w.x);
                fma2(acc2[2*j+1].u, a2, w.y);
            }
        }
    }
    float sigma_raw = acc2[0].f.x;

    // ---- direction components ----
    float dcv[3];
    dcv[0] = dirs[gi * 3 + 0];
    dcv[1] = dirs[gi * 3 + 1];
    dcv[2] = dirs[gi * 3 + 2];

    // ---- color layer 1: 43 -> 64, relu. Weights from __constant__.
    //      2 x 32-output halves; trig recomputed per half (MUFU). ----
    F2 acc3[32];
    #pragma unroll
    for (int h = 0; h < 2; ++h) {
        F2 a3[16];
        {
            const ulonglong2* bb = reinterpret_cast<const ulonglong2*>(sw + OB3 + h * 32);
            #pragma unroll
            for (int j = 0; j < 8; ++j) { a3[2*j].u = bb[j].x; a3[2*j+1].u = bb[j].y; }
        }
        // rows 0..2: raw direction
        #pragma unroll
        for (int c = 0; c < 3; ++c) {
            ull a2v = bcast2(dcv[c]);
            const ull* wr = cW34 + c * 32 + h * 16;
            #pragma unroll
            for (int j = 0; j < 8; ++j) {
                fma2(a3[2*j].u,   a2v, wr[2*j]);
                fma2(a3[2*j+1].u, a2v, wr[2*j+1]);
            }
        }
        // rows 3..14 sin, 15..26 cos (computed on the fly)
        #pragma unroll
        for (int c = 0; c < 3; ++c) {
            #pragma unroll
            for (int f = 0; f < 4; ++f) {
                float ang = dcv[c] * (float)(1 << f);
                ull s2 = bcast2(__sinf(ang));
                const ull* wrs = cW34 + (3 + c*4 + f) * 32 + h * 16;
                #pragma unroll
                for (int j = 0; j < 8; ++j) {
                    fma2(a3[2*j].u,   s2, wrs[2*j]);
                    fma2(a3[2*j+1].u, s2, wrs[2*j+1]);
                }
                ull c2 = bcast2(__cosf(ang));
                const ull* wrc = cW34 + (15 + c*4 + f) * 32 + h * 16;
                #pragma unroll
                for (int j = 0; j < 8; ++j) {
                    fma2(a3[2*j].u,   c2, wrc[2*j]);
                    fma2(a3[2*j+1].u, c2, wrc[2*j+1]);
                }
            }
        }
        // rows 27..42: density features (acc2)
        #pragma unroll
        for (int r = 0; r < 16; ++r) {
            float a = (r & 1) ? acc2[r >> 1].f.y : acc2[r >> 1].f.x;
            ull a2v = bcast2(a);
            const ull* wr = cW34 + (27 + r) * 32 + h * 16;
            #pragma unroll
            for (int j = 0; j < 8; ++j) {
                fma2(a3[2*j].u,   a2v, wr[2*j]);
                fma2(a3[2*j+1].u, a2v, wr[2*j+1]);
            }
        }
        #pragma unroll
        for (int j = 0; j < 16; ++j) {
            a3[j].f.x = fmaxf(a3[j].f.x, 0.0f);
            a3[j].f.y = fmaxf(a3[j].f.y, 0.0f);
            acc3[h * 16 + j] = a3[j];
        }
    }

    // ---- color layer 2 (64->64, relu) fused with layer 3 (64->3):
    //      W4 rows 0..45 from __constant__, rows 46..63 from smem (port balance). ----
    ull vr2 = 0, vg2 = 0, vb2 = 0;
    #pragma unroll
    for (int h = 0; h < 2; ++h) {
        F2 a4[16];
        {
            const ulonglong2* bb = reinterpret_cast<const ulonglong2*>(sw + OB4 + h * 32);
            #pragma unroll
            for (int j = 0; j < 8; ++j) { a4[2*j].u = bb[j].x; a4[2*j+1].u = bb[j].y; }
        }
        #pragma unroll
        for (int i = 0; i < 64; ++i) {
            float a = (i & 1) ? acc3[i >> 1].f.y : acc3[i >> 1].f.x;
            ull a2v = bcast2(a);
            if (i < W4_CONST_ROWS) {
                const ull* wr = cW34 + CW3_ULL + i * 32 + h * 16;
                #pragma unroll
                for (int j = 0; j < 8; ++j) {
                    fma2(a4[2*j].u,   a2v, wr[2*j]);
                    fma2(a4[2*j+1].u, a2v, wr[2*j+1]);
                }
            } else {
                const ulonglong2* wr = reinterpret_cast<const ulonglong2*>(sw + OW4S + (i - W4_CONST_ROWS) * 64 + h * 32);
                #pragma unroll
                for (int j = 0; j < 8; ++j) {
                    ulonglong2 w = wr[j];
                    fma2(a4[2*j].u,   a2v, w.x);
                    fma2(a4[2*j+1].u, a2v, w.y);
                }
            }
        }
        #pragma unroll
        for (int j = 0; j < 16; ++j) {
            a4[j].f.x = fmaxf(a4[j].f.x, 0.0f);
            a4[j].f.y = fmaxf(a4[j].f.y, 0.0f);
        }
        // layer-5 partial dot: outputs [h*32, h*32+32)
        const ulonglong2* wr5r = reinterpret_cast<const ulonglong2*>(sw + OW5T + 0 * 64 + h * 32);
        const ulonglong2* wr5g = reinterpret_cast<const ulonglong2*>(sw + OW5T + 1 * 64 + h * 32);
        const ulonglong2* wr5b = reinterpret_cast<const ulonglong2*>(sw + OW5T + 2 * 64 + h * 32);
        #pragma unroll
        for (int j = 0; j < 8; ++j) {
            ulonglong2 wr_ = wr5r[j];
            fma2(vr2, a4[2*j].u, wr_.x);
            fma2(vr2, a4[2*j+1].u, wr_.y);
            ulonglong2 wg_ = wr5g[j];
            fma2(vg2, a4[2*j].u, wg_.x);
            fma2(vg2, a4[2*j+1].u, wg_.y);
            ulonglong2 wb_ = wr5b[j];
            fma2(vb2, a4[2*j].u, wb_.x);
            fma2(vb2, a4[2*j+1].u, wb_.y);
        }
    }
    F2 tr; tr.u = vr2;
    F2 tg; tg.u = vg2;
    F2 tb_; tb_.u = vb2;
    float vr = tr.f.x + tr.f.y + sw[OB5 + 0];
    float vg = tg.f.x + tg.f.y + sw[OB5 + 1];
    float vb = tb_.f.x + tb_.f.y + sw[OB5 + 2];

    float cr = inside ? 1.0f / (1.0f + __expf(-vr)) : 0.0f;
    float cg = inside ? 1.0f / (1.0f + __expf(-vg)) : 0.0f;
    float cb = inside ? 1.0f / (1.0f + __expf(-vb)) : 0.0f;

    // ---- outputs: [N,3] color then [N] log_sigma ----
    out[gi * 3 + 0] = cr;
    out[gi * 3 + 1] = cg;
    out[gi * 3 + 2] = cb;
    out[(size_t)3 * n + gi] = inside ? sigma_raw : -100000.0f;
}

extern "C" void kernel_launch(void* const* d_in, const int* in_sizes, int n_in,
                              void* d_out, int out_size) {
    const float* x      = (const float*)d_in[0];
    const float* d      = (const float*)d_in[1];
    const float* tables = (const float*)d_in[2];
    const float* w1 = (const float*)d_in[3];
    const float* b1 = (const float*)d_in[4];
    const float* w2 = (const float*)d_in[5];
    const float* b2 = (const float*)d_in[6];
    const float* w3 = (const float*)d_in[7];
    const float* b3 = (const float*)d_in[8];
    const float* w4 = (const float*)d_in[9];
    const float* b4 = (const float*)d_in[10];
    const float* w5 = (const float*)d_in[11];
    const float* b5 = (const float*)d_in[12];
    float* out = (float*)d_out;

    // stage W3 and W4 into constant memory (device-to-device, graph-capturable)
    cudaMemcpyToSymbolAsync(cW34, w3, 2752 * sizeof(float), 0, cudaMemcpyDeviceToDevice, 0);
    cudaMemcpyToSymbolAsync(cW34, w4, 4096 * sizeof(float), CW3_ULL * sizeof(ull), cudaMemcpyDeviceToDevice, 0);

    int n = in_sizes[0] / 3;
    int blocks = (n + 127) / 128;
    ngp_kernel<<<blocks, 128>>>(x, d, tables, w1, b1, w2, b2, b3, w4, b4, w5, b5, out, n);
}